// round 16
// baseline (speedup 1.0000x reference)
#include <cuda_runtime.h>
#include <stdint.h>

#define NB     32
#define CIN    256
#define HDIM   56
#define HW     3136
#define PIXI   100352
#define OC     256
#define HP     58
#define IMGP   (HP*HP)          // 3364
#define NPAD   (NB*IMGP)        // 107648 = 841*128
#define GUARD  72
#define XROWS  (NPAD + 2*GUARD)
#define KTOT   2304
#define NTILES (NPAD/128)       // 841
#define NCHUNK 9
#define OSP    192              // popcount covers o[0,192)
#define OCI    64               // imma covers o[192,256)
#define CH_A   32768            // 128 rows * 256B
#define CH_B   (OCI*256)        // 16384
#define STG2   (CH_A + CH_B)    // 49152
#define WS_OFF  (3*STG2)                // 147456
#define WP_OFF  (WS_OFF + OSP*72*4)     // 202752
#define SMM_OFF (WP_OFF + OSP*9*4)      // 209664
#define SMEMH   (SMM_OFF + 256*4)       // 210688
#define EPI_STRIDE 132

// ---- device scratch ----
__device__ float g_alpha[NB];
__device__ float g_m[OC];
__device__ float g_part2[512*8];
__device__ __align__(256) signed char g_xs[(size_t)XROWS*256];        // padded sign bytes, PRE-SWIZZLED
__device__ __align__(256) signed char g_wsp2[(size_t)NCHUNK*OCI*256]; // imma B planes, o 192..255
__device__ unsigned g_xbits[(size_t)PIXI*8];                          // bit-packed x signs
__device__ unsigned g_wbits[OC*72];                                   // bit-packed w signs
__device__ int      g_wpop[OC*9];

// ===================== helpers =====================
__device__ __forceinline__ uint32_t smem_u32(const void* p) {
    uint32_t a;
    asm("{ .reg .u64 t; cvta.to.shared.u64 t, %1; cvt.u32.u64 %0, t; }" : "=r"(a) : "l"(p));
    return a;
}
__device__ __forceinline__ void mbar_init(uint32_t a, uint32_t cnt) {
    asm volatile("mbarrier.init.shared.b64 [%0], %1;" :: "r"(a), "r"(cnt) : "memory");
}
__device__ __forceinline__ void mbar_expect_tx(uint32_t a, uint32_t tx) {
    asm volatile("mbarrier.arrive.expect_tx.shared.b64 _, [%0], %1;" :: "r"(a), "r"(tx) : "memory");
}
__device__ __forceinline__ void mbar_arrive(uint32_t a) {
    asm volatile("mbarrier.arrive.shared.b64 _, [%0];" :: "r"(a) : "memory");
}
__device__ __forceinline__ void mbar_wait(uint32_t a, uint32_t ph) {
    asm volatile(
        "{ .reg .pred P;\n"
        "WL_%=: mbarrier.try_wait.parity.acquire.cta.shared::cta.b64 P, [%0], %1, 0x989680;\n"
        "@P bra WD_%=;\n"
        "bra WL_%=;\n"
        "WD_%=: }"
        :: "r"(a), "r"(ph) : "memory");
}
__device__ __forceinline__ void bulkcp(uint32_t dst, const void* src, uint32_t bytes, uint32_t mbar) {
    asm volatile("cp.async.bulk.shared::cluster.global.mbarrier::complete_tx::bytes [%0], [%1], %2, [%3];"
                 :: "r"(dst), "l"(src), "r"(bytes), "r"(mbar) : "memory");
}
__device__ __forceinline__ void ldsm4(uint32_t (&r)[4], uint32_t addr) {
    asm volatile("ldmatrix.sync.aligned.m8n8.x4.shared.b16 {%0,%1,%2,%3}, [%4];"
                 : "=r"(r[0]), "=r"(r[1]), "=r"(r[2]), "=r"(r[3]) : "r"(addr));
}
__device__ __forceinline__ void imma_op(int* c, const uint32_t* a, uint32_t b0, uint32_t b1) {
    asm volatile("mma.sync.aligned.m16n8k32.row.col.s32.s8.s8.s32 "
                 "{%0,%1,%2,%3}, {%4,%5,%6,%7}, {%8,%9}, {%0,%1,%2,%3};"
                 : "+r"(c[0]), "+r"(c[1]), "+r"(c[2]), "+r"(c[3])
                 : "r"(a[0]), "r"(a[1]), "r"(a[2]), "r"(a[3]), "r"(b0), "r"(b1));
}

// ===================== L0: fused x pass (read x ONCE) =====================
__global__ void k_fused_x(const float* __restrict__ x) {
    int t = threadIdx.x;
    int bx = blockIdx.x, cg = blockIdx.y;
    int n = bx >> 4, ch = bx & 15;
    bool act = (t < 196);
    int hw = ch * 196 + t;
    float s = 0.f;
    if (act) {
        const float* xp = x + ((size_t)(n * CIN + cg * 32)) * HW + hw;
        unsigned bb[8];
        unsigned word = 0u;
        #pragma unroll
        for (int q = 0; q < 8; q++) {
            unsigned wrd = 0u;
            #pragma unroll
            for (int j = 0; j < 4; j++) {
                float v = xp[(size_t)(q * 4 + j) * HW];
                s += fabsf(v);
                bool pos = (v > 0.f);
                wrd |= (pos ? 0x01u : 0xFFu) << (j * 8);
                if (pos) word |= (1u << (q * 4 + j));
            }
            bb[q] = wrd;
        }
        int h = hw / HDIM, w = hw - h * HDIM;
        size_t row = (size_t)n * IMGP + (size_t)(h + 1) * HP + (w + 1) + GUARD;
        int rb = (int)(row & 7);
        int s0 = cg * 2;
        *(uint4*)(g_xs + row * 256 + (size_t)((s0    ) ^ rb) * 16) = make_uint4(bb[0], bb[1], bb[2], bb[3]);
        *(uint4*)(g_xs + row * 256 + (size_t)((s0 + 1) ^ rb) * 16) = make_uint4(bb[4], bb[5], bb[6], bb[7]);
        g_xbits[(size_t)(n * HW + hw) * 8 + cg] = word;
    }
    __shared__ float sh[7];
    #pragma unroll
    for (int d = 16; d > 0; d >>= 1) s += __shfl_down_sync(0xffffffffu, s, d);
    if ((t & 31) == 0) sh[t >> 5] = s;
    __syncthreads();
    if (t == 0) {
        float tot = 0.f;
        #pragma unroll
        for (int i = 0; i < 7; i++) tot += sh[i];
        g_part2[bx * 8 + cg] = tot;
    }
}

// ===================== L1: weights + border + alpha (722 blocks) =====================
__global__ void k_wab(const float* __restrict__ wt) {
    int bid = blockIdx.x;
    int tid = threadIdx.x;
    if (bid < 256) {
        int o = bid, c = tid;
        const float* wo = wt + (size_t)o * KTOT;
        const float* woc = wo + (size_t)c * 9;
        float v[9];
        float s = 0.f;
        #pragma unroll
        for (int t = 0; t < 9; t++) { v[t] = woc[t]; s += fabsf(v[t]); }
        __shared__ float sh[8];
        __shared__ unsigned pw[72];
        #pragma unroll
        for (int d = 16; d > 0; d >>= 1) s += __shfl_down_sync(0xffffffffu, s, d);
        if ((tid & 31) == 0) sh[tid >> 5] = s;
        __syncthreads();
        if (tid == 0) {
            float t = 0.f;
            #pragma unroll
            for (int i = 0; i < 8; i++) t += sh[i];
            g_m[o] = t / (float)KTOT;
        }
        if (tid < 72) {
            int t = tid / 8, cc = tid % 8;
            unsigned word = 0u;
            #pragma unroll
            for (int j = 0; j < 32; j++)
                if (wo[(cc * 32 + j) * 9 + t] > 0.f) word |= (1u << j);
            g_wbits[o * 72 + t * 8 + cc] = word;
            pw[t * 8 + cc] = (unsigned)__popc(word);
        }
        __syncthreads();
        if (tid < 9) {
            int acc = 0;
            #pragma unroll
            for (int cc = 0; cc < 8; cc++) acc += (int)pw[tid * 8 + cc];
            g_wpop[o * 9 + tid] = acc;
        }
        if (o >= OSP) {
            int ol = o - OSP;
            int half = c >> 7, off = c & 127, seg = off >> 4, bb = off & 15;
            int segp = seg ^ (ol & 7);
            #pragma unroll
            for (int t = 0; t < 9; t++)
                g_wsp2[((size_t)(t * OCI + ol) * 256) + half * 128 + segp * 16 + bb] =
                    (v[t] > 0.f) ? 1 : -1;
        }
    } else if (bid < 721) {
        int i = (bid - 256) * 256 + tid;
        int rowi = i >> 4, seg = i & 15;
        size_t row;
        if (rowi < 2 * GUARD) {
            row = (rowi < GUARD) ? (size_t)rowi : (size_t)(GUARD + NPAD + (rowi - GUARD));
        } else {
            int idx = rowi - 2 * GUARD;
            int n = idx / 228, j = idx - n * 228;
            int hp, wp;
            if (j < 58)       { hp = 0;  wp = j; }
            else if (j < 116) { hp = 57; wp = j - 58; }
            else if (j < 172) { wp = 0;  hp = j - 116 + 1; }
            else              { wp = 57; hp = j - 172 + 1; }
            row = (size_t)GUARD + (size_t)n * IMGP + hp * HP + wp;
        }
        ((uint4*)(g_xs + row * 256))[seg] = make_uint4(0, 0, 0, 0);
    } else {
        if (tid < 32) {
            int n = tid;
            float s = 0.f;
            #pragma unroll
            for (int c = 0; c < 16; c++)
                #pragma unroll
                for (int cg = 0; cg < 8; cg++)
                    s += g_part2[(n * 16 + c) * 8 + cg];
            float a = 2.f * s / (float)(CIN * HW);
            g_alpha[n] = fmaxf(a, 1e-5f);
        }
    }
}

// ===================== L2: hybrid conv (imma o[192,256) + popcount o[0,192)) ====
__global__ void __launch_bounds__(512, 1) k_hybrid(float* __restrict__ out) {
    extern __shared__ char smem[];
    const uint32_t sb = smem_u32(smem);
    __shared__ __align__(8) unsigned long long s_bar[6];
    const uint32_t barb = smem_u32(s_bar);

    const int tid = threadIdx.x;
    const int wid = tid >> 5;
    const int lane = tid & 31;
    const int j0 = blockIdx.x * 128;

    unsigned* ws = (unsigned*)(smem + WS_OFF);
    int* wps = (int*)(smem + WP_OFF);
    float* smm = (float*)(smem + SMM_OFF);

    if (tid == 0) {
        #pragma unroll
        for (int s = 0; s < 3; s++) {
            mbar_init(barb + s * 16, 1);
            mbar_init(barb + s * 16 + 8, 8);
        }
    }
    for (int i = tid; i < OSP * 72; i += 512) ws[i] = g_wbits[i];
    for (int i = tid; i < OSP * 9; i += 512) wps[i] = g_wpop[i];
    if (tid < 256) smm[tid] = g_m[tid];
    __syncthreads();

    if (tid == 0) {
        #pragma unroll
        for (int q = 0; q < 3; q++) {
            uint32_t full = barb + q * 16;
            mbar_expect_tx(full, STG2);
            int od = (q / 3 - 1) * HP + (q % 3 - 1);
            bulkcp(sb + q * STG2, g_xs + ((size_t)(GUARD + j0 + od)) * 256, CH_A, full);
            bulkcp(sb + q * STG2 + CH_A, g_wsp2 + (size_t)q * CH_B, CH_B, full);
        }
    }

    if (tid < 256) {
        // ======== IMMA half: o in [192, 256), warp tile 32x32 ========
        const int warp_m = wid & 3;
        const int warp_n = wid >> 2;
        const int r16   = (lane & 7) + ((lane >> 3) & 1) * 8;
        const int khoff = ((lane >> 4) & 1) * 16;
        const int a_r0  = warp_m * 32 + r16;
        const int b_r0  = warp_n * 32 + r16;
        const int maskB = (lane & 7) * 16;

        int acc[2][4][4];
        #pragma unroll
        for (int m = 0; m < 2; m++)
            #pragma unroll
            for (int g = 0; g < 4; g++)
                #pragma unroll
                for (int k = 0; k < 4; k++) acc[m][g][k] = 0;

        #pragma unroll 1
        for (int q = 0; q < NCHUNK; q++) {
            int s = q % 3;
            mbar_wait(barb + s * 16, (uint32_t)((q / 3) & 1));
            uint32_t sA = sb + s * STG2;
            uint32_t sB = sA + CH_A;
            int od = (q / 3 - 1) * HP + (q % 3 - 1);
            int maskA = ((od + a_r0) & 7) * 16;
            #pragma unroll
            for (int ks = 0; ks < 8; ks++) {
                int half = (ks >> 2) * 128;
                int kh = (ks & 3) * 32 + khoff;
                int kxA = half + (kh ^ maskA);
                int kxB = half + (kh ^ maskB);
                uint32_t af[2][4], bf[2][4];
                ldsm4(af[0], sA + (unsigned)(a_r0 * 256) + kxA);
                ldsm4(af[1], sA + (unsigned)((a_r0 + 16) * 256) + kxA);
                ldsm4(bf[0], sB + (unsigned)(b_r0 * 256) + kxB);
                ldsm4(bf[1], sB + (unsigned)((b_r0 + 16) * 256) + kxB);
                #pragma unroll
                for (int i = 0; i < 2; i++) {
                    imma_op(acc[0][i * 2 + 0], af[0], bf[i][0], bf[i][2]);
                    imma_op(acc[1][i * 2 + 0], af[1], bf[i][0], bf[i][2]);
                    imma_op(acc[0][i * 2 + 1], af[0], bf[i][1], bf[i][3]);
                    imma_op(acc[1][i * 2 + 1], af[1], bf[i][1], bf[i][3]);
                }
            }
            if (lane == 0) mbar_arrive(barb + s * 16 + 8);
            if (tid == 0 && q + 3 < NCHUNK) {
                int qq = q + 3;
                mbar_wait(barb + s * 16 + 8, (uint32_t)(1 - ((qq / 3) & 1)));
                uint32_t full = barb + s * 16;
                mbar_expect_tx(full, STG2);
                int od2 = (qq / 3 - 1) * HP + (qq % 3 - 1);
                bulkcp(sA, g_xs + ((size_t)(GUARD + j0 + od2)) * 256, CH_A, full);
                bulkcp(sB, g_wsp2 + (size_t)qq * CH_B, CH_B, full);
            }
        }

        // epilogue: transpose through low smem (ring fully consumed)
        asm volatile("bar.sync 2, 256;" ::: "memory");
        float* sf = (float*)smem;                       // [64 oc][EPI_STRIDE]
        #pragma unroll
        for (int m = 0; m < 2; m++) {
            int row = warp_m * 32 + m * 16 + (lane >> 2);
            #pragma unroll
            for (int g = 0; g < 4; g++) {
                int col = warp_n * 32 + (g >> 1) * 16 + (g & 1) * 8 + (lane & 3) * 2;
                sf[(col    ) * EPI_STRIDE + row    ] = (float)acc[m][g][0];
                sf[(col + 1) * EPI_STRIDE + row    ] = (float)acc[m][g][1];
                sf[(col    ) * EPI_STRIDE + row + 8] = (float)acc[m][g][2];
                sf[(col + 1) * EPI_STRIDE + row + 8] = (float)acc[m][g][3];
            }
        }
        asm volatile("bar.sync 2, 256;" ::: "memory");

        int p_local = tid & 127, halfq = tid >> 7;      // 2 halves x 32 oc
        int j = j0 + p_local;
        int n = j / IMGP, rem = j - n * IMGP;
        int hp = rem / HP, wq = rem - hp * HP;
        bool inter = (hp >= 1 && hp <= 56 && wq >= 1 && wq <= 56);
        float av = g_alpha[n];
        float* ob = out + ((size_t)n * OC + OSP) * HW + (hp - 1) * HDIM + (wq - 1);
        #pragma unroll 4
        for (int oo = 0; oo < 32; oo++) {
            int ol = halfq * 32 + oo;
            float v = sf[ol * EPI_STRIDE + p_local] * av * smm[OSP + ol];
            if (inter) ob[(size_t)ol * HW] = v;
        }
    } else {
        // ======== popcount half: o in [0, 192), 2 oc at a time, 8 acc chains ====
        int t = tid - 256;
        int px = t & 127;
        int og = t >> 7;                               // 0/1 -> o 0..95 / 96..191
        int j = j0 + px;
        int n = j / IMGP, rem = j - n * IMGP;
        int hp = rem / HP, wq = rem - hp * HP;
        if (hp >= 1 && hp <= 56 && wq >= 1 && wq <= 56) {
            int h = hp - 1, w = wq - 1;
            unsigned xb[72];
            unsigned invmask = 0u;
            #pragma unroll
            for (int tp = 0; tp < 9; tp++) {
                int hh = h + tp / 3 - 1;
                int ww = w + tp % 3 - 1;
                if (hh >= 0 && hh < HDIM && ww >= 0 && ww < HDIM) {
                    const uint4* src = (const uint4*)&g_xbits[((size_t)(n * HW + hh * HDIM + ww)) * 8];
                    uint4 a = src[0], b = src[1];
                    xb[tp*8+0]=a.x; xb[tp*8+1]=a.y; xb[tp*8+2]=a.z; xb[tp*8+3]=a.w;
                    xb[tp*8+4]=b.x; xb[tp*8+5]=b.y; xb[tp*8+6]=b.z; xb[tp*8+7]=b.w;
                } else {
                    invmask |= (1u << tp);
                    #pragma unroll
                    for (int cc = 0; cc < 8; cc++) xb[tp*8+cc] = 0u;
                }
            }
            float av = g_alpha[n];
            float* op = out + ((size_t)n * OC) * HW + h * HDIM + w;
            int o0 = og * 96;
            #pragma unroll 1
            for (int o = o0; o < o0 + 96; o += 2) {
                const uint4* wr0 = (const uint4*)&ws[o * 72];
                const uint4* wr1 = (const uint4*)&ws[(o + 1) * 72];
                int a0 = 0, a1 = 0, a2 = 0, a3 = 0;
                int b0 = 0, b1 = 0, b2 = 0, b3 = 0;
                #pragma unroll
                for (int q = 0; q < 18; q++) {
                    uint4 v0 = wr0[q], v1 = wr1[q];
                    a0 += __popc(xb[q*4+0] ^ v0.x);
                    a1 += __popc(xb[q*4+1] ^ v0.y);
                    a2 += __popc(xb[q*4+2] ^ v0.z);
                    a3 += __popc(xb[q*4+3] ^ v0.w);
                    b0 += __popc(xb[q*4+0] ^ v1.x);
                    b1 += __popc(xb[q*4+1] ^ v1.y);
                    b2 += __popc(xb[q*4+2] ^ v1.z);
                    b3 += __popc(xb[q*4+3] ^ v1.w);
                }
                int dot0 = KTOT - 2 * ((a0 + a1) + (a2 + a3));
                int dot1 = KTOT - 2 * ((b0 + b1) + (b2 + b3));
                if (invmask) {
                    unsigned mm = invmask;
                    while (mm) {
                        int tp = __ffs(mm) - 1; mm &= mm - 1;
                        dot0 -= (256 - 2 * wps[o * 9 + tp]);
                        dot1 -= (256 - 2 * wps[(o + 1) * 9 + tp]);
                    }
                }
                op[(size_t)o * HW]       = av * smm[o]     * (float)dot0;
                op[(size_t)(o + 1) * HW] = av * smm[o + 1] * (float)dot1;
            }
        }
    }
}

// ===================== launch =====================
extern "C" void kernel_launch(void* const* d_in, const int* in_sizes, int n_in,
                              void* d_out, int out_size) {
    const float* x  = (const float*)d_in[0];
    const float* wt = (const float*)d_in[1];
    float* out = (float*)d_out;

    k_fused_x<<<dim3(512, 8), 224>>>(x);
    k_wab<<<722, 256>>>(wt);

    static int smem_set = 0;
    if (!smem_set) {
        cudaFuncSetAttribute(k_hybrid, cudaFuncAttributeMaxDynamicSharedMemorySize, SMEMH);
        smem_set = 1;
    }
    k_hybrid<<<NTILES, 512, SMEMH>>>(out);
}